// round 1
// baseline (speedup 1.0000x reference)
#include <cuda_runtime.h>

// CondConv3d collapses: out[b] = s[b] * (conv3d(x[b], Wsum) + bias_sum)
//   s[b]     = sum_e routing_weights[b,e]
//   Wsum     = sum_e weight[e]  (stored transposed as [c][tap][o])
//   bias_sum = sum_e bias[e]
//
// B=8, C=32, O=32, D=16, H=64, W=64, K=3, PAD=1, E=8

#define B_ 8
#define CIN 32
#define COUT 32
#define DD 16
#define HH_ 64
#define WW 64
#define TAPS 27
#define CC 4     // input-channel chunk
#define TH 4     // h rows per block

__device__ float g_wsum[CIN * TAPS * COUT];  // [c][t][o]
__device__ float g_bias[COUT];
__device__ float g_s[B_];

__global__ void prep_kernel(const float* __restrict__ weight,
                            const float* __restrict__ bias,
                            const float* __restrict__ rw) {
    int idx = blockIdx.x * 256 + threadIdx.x;
    if (idx < CIN * TAPS * COUT) {
        int o = idx & 31;
        int t = (idx >> 5) % TAPS;
        int c = idx / (32 * TAPS);
        // weight layout: [e][o][c][kd][kh][kw]
        int base = (o * CIN + c) * TAPS + t;
        float s = 0.f;
        #pragma unroll
        for (int e = 0; e < 8; e++) s += weight[e * (COUT * CIN * TAPS) + base];
        g_wsum[(c * TAPS + t) * COUT + o] = s;
    }
    if (blockIdx.x == 0) {
        int tid = threadIdx.x;
        if (tid < COUT) {
            float s = 0.f;
            #pragma unroll
            for (int e = 0; e < 8; e++) s += bias[e * COUT + tid];
            g_bias[tid] = s;
        } else if (tid < COUT + B_) {
            int b = tid - COUT;
            float s = 0.f;
            #pragma unroll
            for (int e = 0; e < 8; e++) s += rw[b * 8 + e];
            g_s[b] = s;
        }
    }
}

__global__ __launch_bounds__(256) void conv_kernel(const float* __restrict__ x,
                                                   float* __restrict__ out) {
    // smem tiles
    __shared__ float xs[CC][3][TH + 2][68];   // [cl][dz][row][w(66 used, pad 68)]
    __shared__ float ws[CC][TAPS][COUT];      // [cl][tap][o]

    const int tid = threadIdx.x;
    const int hh = tid >> 6;          // 0..3  output row within tile
    const int og = (tid >> 3) & 7;    // 0..7  group of 4 output channels
    const int wg = tid & 7;           // 0..7  group of 8 w positions
    const int w0 = wg * 8;

    const int h0 = blockIdx.x * TH;
    const int d  = blockIdx.y;
    const int b  = blockIdx.z;

    const float* __restrict__ xb = x + (size_t)b * CIN * DD * HH_ * WW;

    float acc[4][8];
    #pragma unroll
    for (int i = 0; i < 4; i++)
        #pragma unroll
        for (int j = 0; j < 8; j++) acc[i][j] = 0.f;

    #pragma unroll 1
    for (int ch = 0; ch < CIN / CC; ch++) {
        __syncthreads();
        // ---- load weight chunk (contiguous slab, coalesced) ----
        #pragma unroll 1
        for (int i = tid; i < CC * TAPS * COUT; i += 256) {
            ((float*)ws)[i] = g_wsum[ch * (CC * TAPS * COUT) + i];
        }
        // ---- load input tile with zero-padded halos ----
        #pragma unroll 1
        for (int i = tid; i < CC * 3 * (TH + 2) * 66; i += 256) {
            int w  = i % 66;                    // smem column 0..65, gw = w-1
            int r  = i / 66;
            int rr = r % (TH + 2);              // row in tile
            int dz = (r / (TH + 2)) % 3;
            int cl = r / (3 * (TH + 2));
            int gw = w - 1;
            int gh = h0 - 1 + rr;
            int gd = d - 1 + dz;
            float v = 0.f;
            if (gw >= 0 && gw < WW && gh >= 0 && gh < HH_ && gd >= 0 && gd < DD) {
                int c = ch * CC + cl;
                v = xb[((c * DD + gd) * HH_ + gh) * WW + gw];
            }
            xs[cl][dz][rr][w] = v;
        }
        __syncthreads();
        // ---- compute ----
        #pragma unroll 1
        for (int cl = 0; cl < CC; cl++) {
            #pragma unroll
            for (int kd = 0; kd < 3; kd++) {
                #pragma unroll
                for (int kh = 0; kh < 3; kh++) {
                    float xin[10];
                    #pragma unroll
                    for (int i = 0; i < 10; i++)
                        xin[i] = xs[cl][kd][hh + kh][w0 + i];
                    #pragma unroll
                    for (int kw = 0; kw < 3; kw++) {
                        const int t = kd * 9 + kh * 3 + kw;
                        #pragma unroll
                        for (int oi = 0; oi < 4; oi++) {
                            float wt = ws[cl][t][og * 4 + oi];
                            #pragma unroll
                            for (int wi = 0; wi < 8; wi++)
                                acc[oi][wi] = fmaf(wt, xin[wi + kw], acc[oi][wi]);
                        }
                    }
                }
            }
        }
    }

    // ---- epilogue: scale + bias, vector stores ----
    const float sb = g_s[b];
    const int h = h0 + hh;
    #pragma unroll
    for (int oi = 0; oi < 4; oi++) {
        const int o = og * 4 + oi;
        const float bs = g_bias[o];
        float4 v0, v1;
        v0.x = sb * (acc[oi][0] + bs);
        v0.y = sb * (acc[oi][1] + bs);
        v0.z = sb * (acc[oi][2] + bs);
        v0.w = sb * (acc[oi][3] + bs);
        v1.x = sb * (acc[oi][4] + bs);
        v1.y = sb * (acc[oi][5] + bs);
        v1.z = sb * (acc[oi][6] + bs);
        v1.w = sb * (acc[oi][7] + bs);
        float* op = out + (((size_t)(b * COUT + o) * DD + d) * HH_ + h) * WW + w0;
        *reinterpret_cast<float4*>(op) = v0;
        *reinterpret_cast<float4*>(op + 4) = v1;
    }
}

extern "C" void kernel_launch(void* const* d_in, const int* in_sizes, int n_in,
                              void* d_out, int out_size) {
    // Map inputs by element count (robust to ordering):
    // x: 8*32*16*64*64 = 16777216, rw: 64, weight: 8*32*32*27 = 221184, bias: 256
    const float *x = nullptr, *rw = nullptr, *wt = nullptr, *bi = nullptr;
    for (int i = 0; i < n_in; i++) {
        if (in_sizes[i] == 16777216)     x  = (const float*)d_in[i];
        else if (in_sizes[i] == 221184)  wt = (const float*)d_in[i];
        else if (in_sizes[i] == 256)     bi = (const float*)d_in[i];
        else if (in_sizes[i] == 64)      rw = (const float*)d_in[i];
    }
    float* out = (float*)d_out;

    prep_kernel<<<(CIN * TAPS * COUT + 255) / 256, 256>>>(wt, bi, rw);

    dim3 grid(HH_ / TH, DD, B_);   // (16, 16, 8) = 2048 blocks
    conv_kernel<<<grid, 256>>>(x, out);
}

// round 2
// speedup vs baseline: 1.8134x; 1.8134x over previous
#include <cuda_runtime.h>

// CondConv3d collapses: out[b] = s[b] * (conv3d(x[b], Wsum) + bias_sum)
//   s[b]     = sum_e routing_weights[b,e]
//   Wsum     = sum_e weight[e]  (stored transposed as [c][tap][o])
//   bias_sum = sum_e bias[e]
//
// B=8, C=32, O=32, D=16, H=64, W=64, K=3, PAD=1, E=8
// Round 2: packed fp32x2 FMA (FFMA2) with output-channel-pair lanes.

#define B_ 8
#define CIN 32
#define COUT 32
#define DD 16
#define HH_ 64
#define WW 64
#define TAPS 27
#define CC 4     // input-channel chunk
#define TH 4     // h rows per block

__device__ float g_wsum[CIN * TAPS * COUT];  // [c][t][o]
__device__ float g_bias[COUT];
__device__ float g_s[B_];

__global__ void prep_kernel(const float* __restrict__ weight,
                            const float* __restrict__ bias,
                            const float* __restrict__ rw) {
    int idx = blockIdx.x * 256 + threadIdx.x;
    if (idx < CIN * TAPS * COUT) {
        int o = idx & 31;
        int t = (idx >> 5) % TAPS;
        int c = idx / (32 * TAPS);
        // weight layout: [e][o][c][kd][kh][kw]
        int base = (o * CIN + c) * TAPS + t;
        float s = 0.f;
        #pragma unroll
        for (int e = 0; e < 8; e++) s += weight[e * (COUT * CIN * TAPS) + base];
        g_wsum[(c * TAPS + t) * COUT + o] = s;
    }
    if (blockIdx.x == 0) {
        int tid = threadIdx.x;
        if (tid < COUT) {
            float s = 0.f;
            #pragma unroll
            for (int e = 0; e < 8; e++) s += bias[e * COUT + tid];
            g_bias[tid] = s;
        } else if (tid < COUT + B_) {
            int b = tid - COUT;
            float s = 0.f;
            #pragma unroll
            for (int e = 0; e < 8; e++) s += rw[b * 8 + e];
            g_s[b] = s;
        }
    }
}

// ---- packed f32x2 helpers (ptxas never emits FFMA2 from C++) ----
__device__ __forceinline__ unsigned long long bcast2(float v) {
    unsigned long long r;
    asm("mov.b64 %0, {%1, %1};" : "=l"(r) : "f"(v));
    return r;
}
__device__ __forceinline__ void ffma2(unsigned long long& d,
                                      unsigned long long a,
                                      unsigned long long b) {
    asm("fma.rn.f32x2 %0, %1, %2, %0;" : "+l"(d) : "l"(a), "l"(b));
}
__device__ __forceinline__ void unpack2(unsigned long long v, float& lo, float& hi) {
    asm("mov.b64 {%0, %1}, %2;" : "=f"(lo), "=f"(hi) : "l"(v));
}

__global__ __launch_bounds__(256) void conv_kernel(const float* __restrict__ x,
                                                   float* __restrict__ out) {
    __shared__ float xs[CC][3][TH + 2][68];   // [cl][dz][row][w(66 used, pad 68)]
    __shared__ float ws[CC][TAPS][COUT];      // [cl][tap][o] — o contiguous -> LDS.64 pairs

    const int tid = threadIdx.x;
    const int hh = tid >> 6;          // 0..3  output row within tile
    const int og = (tid >> 3) & 7;    // 0..7  group of 4 output channels
    const int wg = tid & 7;           // 0..7  group of 8 w positions
    const int w0 = wg * 8;

    const int h0 = blockIdx.x * TH;
    const int d  = blockIdx.y;
    const int b  = blockIdx.z;

    const float* __restrict__ xb = x + (size_t)b * CIN * DD * HH_ * WW;

    // acc2[op][wi]: f32x2 accumulator, lanes = output channels (og*4+2*op, +1)
    unsigned long long acc2[2][8];
    #pragma unroll
    for (int op = 0; op < 2; op++)
        #pragma unroll
        for (int wi = 0; wi < 8; wi++) acc2[op][wi] = 0ull;

    #pragma unroll 1
    for (int ch = 0; ch < CIN / CC; ch++) {
        __syncthreads();
        // ---- load weight chunk (contiguous slab, coalesced) ----
        #pragma unroll 1
        for (int i = tid; i < CC * TAPS * COUT; i += 256) {
            ((float*)ws)[i] = g_wsum[ch * (CC * TAPS * COUT) + i];
        }
        // ---- load input tile with zero-padded halos ----
        #pragma unroll 1
        for (int i = tid; i < CC * 3 * (TH + 2) * 66; i += 256) {
            int w  = i % 66;                    // smem column 0..65, gw = w-1
            int r  = i / 66;
            int rr = r % (TH + 2);              // row in tile
            int dz = (r / (TH + 2)) % 3;
            int cl = r / (3 * (TH + 2));
            int gw = w - 1;
            int gh = h0 - 1 + rr;
            int gd = d - 1 + dz;
            float v = 0.f;
            if (gw >= 0 && gw < WW && gh >= 0 && gh < HH_ && gd >= 0 && gd < DD) {
                int c = ch * CC + cl;
                v = xb[((c * DD + gd) * HH_ + gh) * WW + gw];
            }
            xs[cl][dz][rr][w] = v;
        }
        __syncthreads();
        // ---- compute: FFMA2, o-pair lanes ----
        #pragma unroll 1
        for (int cl = 0; cl < CC; cl++) {
            #pragma unroll
            for (int kd = 0; kd < 3; kd++) {
                #pragma unroll
                for (int kh = 0; kh < 3; kh++) {
                    // broadcast x scalars into both f32x2 lanes
                    unsigned long long xp[10];
                    #pragma unroll
                    for (int i = 0; i < 10; i++)
                        xp[i] = bcast2(xs[cl][kd][hh + kh][w0 + i]);
                    #pragma unroll
                    for (int kw = 0; kw < 3; kw++) {
                        const int t = kd * 9 + kh * 3 + kw;
                        #pragma unroll
                        for (int op = 0; op < 2; op++) {
                            // natural 8B weight pair from smem (LDS.64, no pack)
                            const unsigned long long wp =
                                *reinterpret_cast<const unsigned long long*>(
                                    &ws[cl][t][og * 4 + op * 2]);
                            #pragma unroll
                            for (int wi = 0; wi < 8; wi++)
                                ffma2(acc2[op][wi], wp, xp[wi + kw]);
                        }
                    }
                }
            }
        }
    }

    // ---- epilogue: unpack, scale + bias, vector stores ----
    const float sb = g_s[b];
    const int h = h0 + hh;
    float accs[4][8];
    #pragma unroll
    for (int op = 0; op < 2; op++)
        #pragma unroll
        for (int wi = 0; wi < 8; wi++)
            unpack2(acc2[op][wi], accs[op * 2][wi], accs[op * 2 + 1][wi]);

    #pragma unroll
    for (int oi = 0; oi < 4; oi++) {
        const int o = og * 4 + ((oi >> 1) * 2) + (oi & 1);  // og*4 + oi (pair order)
        const float bs = g_bias[o];
        float4 v0, v1;
        v0.x = sb * (accs[oi][0] + bs);
        v0.y = sb * (accs[oi][1] + bs);
        v0.z = sb * (accs[oi][2] + bs);
        v0.w = sb * (accs[oi][3] + bs);
        v1.x = sb * (accs[oi][4] + bs);
        v1.y = sb * (accs[oi][5] + bs);
        v1.z = sb * (accs[oi][6] + bs);
        v1.w = sb * (accs[oi][7] + bs);
        float* op_ = out + (((size_t)(b * COUT + o) * DD + d) * HH_ + h) * WW + w0;
        *reinterpret_cast<float4*>(op_) = v0;
        *reinterpret_cast<float4*>(op_ + 4) = v1;
    }
}

extern "C" void kernel_launch(void* const* d_in, const int* in_sizes, int n_in,
                              void* d_out, int out_size) {
    // x: 16777216, rw: 64, weight: 221184, bias: 256
    const float *x = nullptr, *rw = nullptr, *wt = nullptr, *bi = nullptr;
    for (int i = 0; i < n_in; i++) {
        if (in_sizes[i] == 16777216)     x  = (const float*)d_in[i];
        else if (in_sizes[i] == 221184)  wt = (const float*)d_in[i];
        else if (in_sizes[i] == 256)     bi = (const float*)d_in[i];
        else if (in_sizes[i] == 64)      rw = (const float*)d_in[i];
    }
    float* out = (float*)d_out;

    prep_kernel<<<(CIN * TAPS * COUT + 255) / 256, 256>>>(wt, bi, rw);

    dim3 grid(HH_ / TH, DD, B_);   // (16, 16, 8) = 2048 blocks
    conv_kernel<<<grid, 256>>>(x, out);
}

// round 3
// speedup vs baseline: 2.4846x; 1.3702x over previous
#include <cuda_runtime.h>
#include <cstdint>

// CondConv3d collapses: out[b] = s[b] * (conv3d(x[b], Wsum) + bias_sum)
// Round 3: cp.async double-buffered pipeline, hoisted addressing, vector LDS,
//          FFMA2 (f32x2) compute with output-channel-pair lanes.

#define B_ 8
#define CIN 32
#define COUT 32
#define DD 16
#define HH_ 64
#define WW 64
#define TAPS 27
#define CC 4     // input-channel chunk
#define TH 4     // h rows per block
#define NCHUNK (CIN / CC)          // 8
#define XROWS (CC * 3 * (TH + 2))  // 72 rows of 66 valid (pitch 68)
#define XELEMS (XROWS * 66)        // 4752 loads per chunk
#define XPITCH 68
#define XS_FLOATS (XROWS * XPITCH) // 4896
#define WS_FLOATS (CC * TAPS * COUT) // 3456
#define STAGE_FLOATS (XS_FLOATS + WS_FLOATS) // 8352
#define NXK 19                     // ceil(4752/256)

__device__ float g_wsum[CIN * TAPS * COUT];  // [c][t][o]
__device__ float g_bias[COUT];
__device__ float g_s[B_];

__global__ void prep_kernel(const float* __restrict__ weight,
                            const float* __restrict__ bias,
                            const float* __restrict__ rw) {
    int idx = blockIdx.x * 256 + threadIdx.x;
    if (idx < CIN * TAPS * COUT) {
        int o = idx & 31;
        int t = (idx >> 5) % TAPS;
        int c = idx / (32 * TAPS);
        int base = (o * CIN + c) * TAPS + t;   // weight: [e][o][c][t]
        float s = 0.f;
        #pragma unroll
        for (int e = 0; e < 8; e++) s += weight[e * (COUT * CIN * TAPS) + base];
        g_wsum[(c * TAPS + t) * COUT + o] = s;
    }
    if (blockIdx.x == 0) {
        int tid = threadIdx.x;
        if (tid < COUT) {
            float s = 0.f;
            #pragma unroll
            for (int e = 0; e < 8; e++) s += bias[e * COUT + tid];
            g_bias[tid] = s;
        } else if (tid < COUT + B_) {
            int b = tid - COUT;
            float s = 0.f;
            #pragma unroll
            for (int e = 0; e < 8; e++) s += rw[b * 8 + e];
            g_s[b] = s;
        }
    }
}

// ---- packed f32x2 helpers ----
__device__ __forceinline__ unsigned long long bcast2(float v) {
    unsigned long long r;
    asm("mov.b64 %0, {%1, %1};" : "=l"(r) : "f"(v));
    return r;
}
__device__ __forceinline__ void ffma2(unsigned long long& d,
                                      unsigned long long a,
                                      unsigned long long b) {
    asm("fma.rn.f32x2 %0, %1, %2, %0;" : "+l"(d) : "l"(a), "l"(b));
}
__device__ __forceinline__ void unpack2(unsigned long long v, float& lo, float& hi) {
    asm("mov.b64 {%0, %1}, %2;" : "=f"(lo), "=f"(hi) : "l"(v));
}

// ---- cp.async helpers ----
__device__ __forceinline__ void cp4_zfill(uint32_t saddr, const float* g, int srcsz) {
    asm volatile("cp.async.ca.shared.global [%0], [%1], 4, %2;"
                 :: "r"(saddr), "l"(g), "r"(srcsz));
}
__device__ __forceinline__ void cp16(uint32_t saddr, const float* g) {
    asm volatile("cp.async.cg.shared.global [%0], [%1], 16;"
                 :: "r"(saddr), "l"(g));
}
__device__ __forceinline__ void cp_commit() {
    asm volatile("cp.async.commit_group;");
}
__device__ __forceinline__ void cp_wait1() {
    asm volatile("cp.async.wait_group 1;");
}
__device__ __forceinline__ void cp_wait0() {
    asm volatile("cp.async.wait_group 0;");
}

extern __shared__ float smem_dyn[];

__global__ __launch_bounds__(256, 2) void conv_kernel(const float* __restrict__ x,
                                                      float* __restrict__ out) {
    const int tid = threadIdx.x;
    const int hh = tid >> 6;          // 0..3
    const int og = (tid >> 3) & 7;    // 0..7
    const int wg = tid & 7;           // 0..7
    const int w0 = wg * 8;

    const int h0 = blockIdx.x * TH;
    const int d  = blockIdx.y;
    const int b  = blockIdx.z;

    const float* __restrict__ xb = x + (size_t)b * CIN * DD * HH_ * WW;

    const uint32_t smem_u32 = (uint32_t)__cvta_generic_to_shared(smem_dyn);

    // ---- hoisted x-tile addressing (per-thread, constant across chunks) ----
    int  goff[NXK];        // float offset into xb (ch=0); 0 when invalid
    uint32_t soff[NXK];    // byte offset of smem dest within xs stage
    unsigned mrange = 0;   // bit k: this k has a tile slot (issue a cp)
    unsigned mvalid = 0;   // bit k: in-bounds (srcsize 4 vs 0)
    #pragma unroll
    for (int k = 0; k < NXK; k++) {
        int i = tid + 256 * k;
        int w = i % 66;
        int r = i / 66;
        int rr = r % (TH + 2);
        int dz = (r / (TH + 2)) % 3;
        int cl = r / (3 * (TH + 2));
        int gw = w - 1;
        int gh = h0 - 1 + rr;
        int gd = d - 1 + dz;
        bool inr = (i < XELEMS);
        bool val = inr && (gw >= 0) && (gw < WW) && (gh >= 0) && (gh < HH_) &&
                   (gd >= 0) && (gd < DD);
        goff[k] = val ? (((cl * DD + gd) * HH_ + gh) * WW + gw) : 0;
        soff[k] = (uint32_t)((((cl * 3 + dz) * (TH + 2) + rr) * XPITCH + w) * 4);
        if (inr) mrange |= 1u << k;
        if (val) mvalid |= 1u << k;
    }

    // ---- prefetch chunk 0 ----
    {
        const float* gx = xb;                       // ch = 0
        uint32_t xs_u = smem_u32;                   // stage 0 xs
        uint32_t ws_u = smem_u32 + XS_FLOATS * 4;   // stage 0 ws
        #pragma unroll
        for (int k = 0; k < NXK; k++) {
            if ((mrange >> k) & 1)
                cp4_zfill(xs_u + soff[k], gx + goff[k], ((mvalid >> k) & 1) * 4);
        }
        const float* gw4 = g_wsum;                  // chunk 0 base
        #pragma unroll
        for (int k = 0; k < 4; k++) {
            int idx = tid + k * 256;                // float4 index, total 864
            if (idx < WS_FLOATS / 4)
                cp16(ws_u + idx * 16, gw4 + idx * 4);
        }
        cp_commit();
    }

    // acc2[op][wi]: lanes = output channels (og*4+2*op, +1)
    unsigned long long acc2[2][8];
    #pragma unroll
    for (int op = 0; op < 2; op++)
        #pragma unroll
        for (int wi = 0; wi < 8; wi++) acc2[op][wi] = 0ull;

    #pragma unroll 1
    for (int ch = 0; ch < NCHUNK; ch++) {
        const int stage = ch & 1;
        // ---- prefetch next chunk into the other stage ----
        if (ch + 1 < NCHUNK) {
            const int ns = (ch + 1) & 1;
            const float* gx = xb + (size_t)(ch + 1) * CC * DD * HH_ * WW;
            uint32_t xs_u = smem_u32 + ns * STAGE_FLOATS * 4;
            uint32_t ws_u = xs_u + XS_FLOATS * 4;
            #pragma unroll
            for (int k = 0; k < NXK; k++) {
                if ((mrange >> k) & 1)
                    cp4_zfill(xs_u + soff[k], gx + goff[k], ((mvalid >> k) & 1) * 4);
            }
            const float* gw4 = g_wsum + (ch + 1) * WS_FLOATS;
            #pragma unroll
            for (int k = 0; k < 4; k++) {
                int idx = tid + k * 256;
                if (idx < WS_FLOATS / 4)
                    cp16(ws_u + idx * 16, gw4 + idx * 4);
            }
            cp_commit();
            cp_wait1();   // current chunk's group done; next still in flight
        } else {
            cp_wait0();
        }
        __syncthreads();

        const float* xsb = smem_dyn + stage * STAGE_FLOATS;
        const float* wsb = xsb + XS_FLOATS;

        // ---- compute ----
        #pragma unroll 1
        for (int cl = 0; cl < CC; cl++) {
            #pragma unroll
            for (int kd = 0; kd < 3; kd++) {
                #pragma unroll
                for (int kh = 0; kh < 3; kh++) {
                    const float* row =
                        xsb + (((cl * 3 + kd) * (TH + 2)) + hh + kh) * XPITCH + w0;
                    // vector loads: 10 floats as 4+4+2
                    float4 a0 = *reinterpret_cast<const float4*>(row);
                    float4 a1 = *reinterpret_cast<const float4*>(row + 4);
                    float2 a2 = *reinterpret_cast<const float2*>(row + 8);
                    unsigned long long xp[10];
                    xp[0] = bcast2(a0.x); xp[1] = bcast2(a0.y);
                    xp[2] = bcast2(a0.z); xp[3] = bcast2(a0.w);
                    xp[4] = bcast2(a1.x); xp[5] = bcast2(a1.y);
                    xp[6] = bcast2(a1.z); xp[7] = bcast2(a1.w);
                    xp[8] = bcast2(a2.x); xp[9] = bcast2(a2.y);
                    #pragma unroll
                    for (int kw = 0; kw < 3; kw++) {
                        const int t = kd * 9 + kh * 3 + kw;
                        #pragma unroll
                        for (int op = 0; op < 2; op++) {
                            const unsigned long long wp =
                                *reinterpret_cast<const unsigned long long*>(
                                    wsb + (cl * TAPS + t) * COUT + og * 4 + op * 2);
                            #pragma unroll
                            for (int wi = 0; wi < 8; wi++)
                                ffma2(acc2[op][wi], wp, xp[wi + kw]);
                        }
                    }
                }
            }
        }
        __syncthreads();
    }

    // ---- epilogue ----
    const float sb = g_s[b];
    const int h = h0 + hh;
    float accs[4][8];
    #pragma unroll
    for (int op = 0; op < 2; op++)
        #pragma unroll
        for (int wi = 0; wi < 8; wi++)
            unpack2(acc2[op][wi], accs[op * 2][wi], accs[op * 2 + 1][wi]);

    #pragma unroll
    for (int oi = 0; oi < 4; oi++) {
        const int o = og * 4 + oi;
        const float bs = g_bias[o];
        float4 v0, v1;
        v0.x = sb * (accs[oi][0] + bs);
        v0.y = sb * (accs[oi][1] + bs);
        v0.z = sb * (accs[oi][2] + bs);
        v0.w = sb * (accs[oi][3] + bs);
        v1.x = sb * (accs[oi][4] + bs);
        v1.y = sb * (accs[oi][5] + bs);
        v1.z = sb * (accs[oi][6] + bs);
        v1.w = sb * (accs[oi][7] + bs);
        float* op_ = out + (((size_t)(b * COUT + o) * DD + d) * HH_ + h) * WW + w0;
        *reinterpret_cast<float4*>(op_) = v0;
        *reinterpret_cast<float4*>(op_ + 4) = v1;
    }
}

extern "C" void kernel_launch(void* const* d_in, const int* in_sizes, int n_in,
                              void* d_out, int out_size) {
    // x: 16777216, rw: 64, weight: 221184, bias: 256
    const float *x = nullptr, *rw = nullptr, *wt = nullptr, *bi = nullptr;
    for (int i = 0; i < n_in; i++) {
        if (in_sizes[i] == 16777216)     x  = (const float*)d_in[i];
        else if (in_sizes[i] == 221184)  wt = (const float*)d_in[i];
        else if (in_sizes[i] == 256)     bi = (const float*)d_in[i];
        else if (in_sizes[i] == 64)      rw = (const float*)d_in[i];
    }
    float* out = (float*)d_out;

    static bool attr_set = false;
    if (!attr_set) {
        cudaFuncSetAttribute(conv_kernel,
                             cudaFuncAttributeMaxDynamicSharedMemorySize,
                             2 * STAGE_FLOATS * 4);
        attr_set = true;
    }

    prep_kernel<<<(CIN * TAPS * COUT + 255) / 256, 256>>>(wt, bi, rw);

    dim3 grid(HH_ / TH, DD, B_);   // (16, 16, 8)
    conv_kernel<<<grid, 256, 2 * STAGE_FLOATS * 4>>>(x, out);
}